// round 7
// baseline (speedup 1.0000x reference)
#include <cuda_runtime.h>

// ---------------- problem constants ----------------
#define BB    4
#define DIM   64
#define RANK  32
#define EE    4
#define HH    256
#define WW    256
#define HWSZ  65536
#define NPIX  262144

// ---------------- device scratch ----------------
__device__ float g_gate[NPIX];
__device__ int   g_idx[NPIX];
__device__ float g_W[4 * 96 * 64];           // fused [Wq;Wkv] per expert
__device__ float g_W2[4 * 64 * 32];          // ow @ p2w per expert
__device__ float g_pre[(size_t)NPIX * 96];   // [p][0:32)=qpre, [32:96)=kvpre
__device__ float g_av [(size_t)NPIX * 64];   // [p][0:32)=attn, [32:64)=v
__device__ float g_ox [(size_t)NPIX * 64];   // ow @ x, pixel-major

// ---------------- prep: fold weight products ----------------
__global__ void k_prep(const float* __restrict__ qw,
                       const float* __restrict__ kvw,
                       const float* __restrict__ p0,
                       const float* __restrict__ p2w,
                       const float* __restrict__ ow) {
    int i = blockIdx.x * blockDim.x + threadIdx.x;     // < 32768
    if (i < 24576) {
        int e = i / 6144;
        int rem = i - e * 6144;
        int o = rem >> 6, c = rem & 63;
        const float* p0e = p0 + e * 2048;
        float acc = 0.f;
        if (o < 32) {
            const float* qe = qw + e * 1024 + o * 32;
            #pragma unroll
            for (int r = 0; r < 32; r++) acc += qe[r] * p0e[r * 64 + c];
        } else {
            const float* ke = kvw + e * 2048 + (o - 32) * 32;
            #pragma unroll
            for (int r = 0; r < 32; r++) acc += ke[r] * p0e[r * 64 + c];
        }
        g_W[i] = acc;
    } else {
        int j = i - 24576;                             // < 8192
        int e = j >> 11;
        int rem = j & 2047;
        int o = rem >> 5, r = rem & 31;
        const float* p2e = p2w + e * 2048;
        const float* owr = ow + o * 64;
        float acc = 0.f;
        #pragma unroll
        for (int c = 0; c < 64; c++) acc += owr[c] * p2e[c * 32 + r];
        g_W2[e * 2048 + o * 32 + r] = acc;
    }
}

// ---------------- AR: fused router + 1x1 conv -> g_pre ----------------
__global__ __launch_bounds__(256) void k_AR(const float* __restrict__ x,
                                            const float* __restrict__ rw,
                                            const float* __restrict__ rb) {
    extern __shared__ float sW[];     // 24576 W | 256 rw | 4 rb
    int tid = threadIdx.x;
    for (int i = tid; i < 24576; i += 256) sW[i] = g_W[i];
    if (tid < 256) sW[24576 + tid] = rw[tid];
    if (tid < 4)   sW[24832 + tid] = rb[tid];
    __syncthreads();

    int p = blockIdx.x * 256 + tid;
    int b = p >> 16, s = p & 0xFFFF;
    const float* xb = x + ((size_t)b * DIM) * HWSZ + s;
    float xv[64];
    #pragma unroll
    for (int c = 0; c < 64; c++) xv[c] = xb[(size_t)c * HWSZ];

    const float* srw = sW + 24576;
    float l0 = sW[24832], l1 = sW[24833], l2 = sW[24834], l3 = sW[24835];
    #pragma unroll
    for (int c = 0; c < 64; c++) {
        float v = xv[c];
        l0 += srw[c] * v; l1 += srw[64 + c] * v;
        l2 += srw[128 + c] * v; l3 += srw[192 + c] * v;
    }
    float lm = l0; int am = 0;
    if (l1 > lm) { lm = l1; am = 1; }
    if (l2 > lm) { lm = l2; am = 2; }
    if (l3 > lm) { lm = l3; am = 3; }
    float m = 1.0f / (expf(l0 - lm) + expf(l1 - lm) + expf(l2 - lm) + expf(l3 - lm));
    g_gate[p] = m;
    g_idx[p]  = am;

    #pragma unroll
    for (int c = 0; c < 64; c++) xv[c] *= m;

    const float4* Wv = (const float4*)(sW + am * 6144);
    float* op = g_pre + (size_t)p * 96;
    #pragma unroll 2
    for (int og = 0; og < 24; og++) {
        float r[4];
        #pragma unroll
        for (int u = 0; u < 4; u++) {
            const float4* wr = Wv + (og * 4 + u) * 16;
            float acc = 0.f;
            #pragma unroll
            for (int j = 0; j < 16; j++) {
                float4 w = wr[j];
                acc += w.x * xv[4*j] + w.y * xv[4*j+1] + w.z * xv[4*j+2] + w.w * xv[4*j+3];
            }
            r[u] = acc;
        }
        *(float4*)(op + og * 4) = make_float4(r[0], r[1], r[2], r[3]);
    }
}

// ---------------- OX: dense ow @ x -> g_ox (pixel-major) ----------------
__global__ __launch_bounds__(256) void k_OX(const float* __restrict__ x,
                                            const float* __restrict__ ow) {
    __shared__ float sW[4096];
    int tid = threadIdx.x;
    for (int i = tid; i < 4096; i += 256) sW[i] = ow[i];
    __syncthreads();
    int p = blockIdx.x * 256 + tid;
    int b = p >> 16, s = p & 0xFFFF;
    const float* xb = x + ((size_t)b * DIM) * HWSZ + s;
    float xv[64];
    #pragma unroll
    for (int c = 0; c < 64; c++) xv[c] = xb[(size_t)c * HWSZ];
    float* op = g_ox + (size_t)p * 64;
    #pragma unroll 2
    for (int og = 0; og < 16; og++) {
        float r[4];
        #pragma unroll
        for (int u = 0; u < 4; u++) {
            const float4* wr = (const float4*)(sW + (og * 4 + u) * 64);
            float acc = 0.f;
            #pragma unroll
            for (int j = 0; j < 16; j++) {
                float4 w = wr[j];
                acc += w.x * xv[4*j] + w.y * xv[4*j+1] + w.z * xv[4*j+2] + w.w * xv[4*j+3];
            }
            r[u] = acc;
        }
        *(float4*)(op + og * 4) = make_float4(r[0], r[1], r[2], r[3]);
    }
}

// ---------------- B: fused masked dwconv(3,7) + patch circular conv ----------------
#define OFF_KV   0          // 196*64 = 12544
#define OFF_QT   12544      // 100*32 = 3200
#define OFF_QE   15744      // 4*2081
#define OFF_KE   24068      // 4*2081
#define OFF_OUT  32392      // 64*68
#define OFF_W7   36744      // 4*64*49
#define OFF_W3   49288      // 4*32*9
#define OFF_B7   50440      // 256
#define OFF_B3   50696      // 128
#define OFF_IDX  50824      // 196 ints
#define SMEM_B_FLOATS 51020
#define ESTRIDE  2081

__global__ __launch_bounds__(512) void k_B(const float* __restrict__ qdww,
                                           const float* __restrict__ qdwb,
                                           const float* __restrict__ kvdww,
                                           const float* __restrict__ kvdwb) {
    extern __shared__ float sm[];
    int* sIdx = (int*)(sm + OFF_IDX);
    int tid = threadIdx.x;
    int blk = blockIdx.x;
    int b = blk >> 10, sp = blk & 1023, ph = sp >> 5, pw = sp & 31;
    int y0 = ph * 8 - 3, x0 = pw * 8 - 3;

    for (int i = tid; i < 12544; i += 512) sm[OFF_W7 + i] = kvdww[i];
    for (int i = tid; i < 1152;  i += 512) sm[OFF_W3 + i] = qdww[i];
    if (tid < 256) sm[OFF_B7 + tid] = kvdwb[tid];
    if (tid < 128) sm[OFF_B3 + tid] = qdwb[tid];

    for (int i = tid; i < 196; i += 512) {
        int hy = i / 14, hx = i - hy * 14;
        int gy = y0 + hy, gx = x0 + hx;
        sIdx[i] = (gy >= 0 && gy < HH && gx >= 0 && gx < WW)
                ? g_idx[b * HWSZ + gy * WW + gx] : -1;
    }
    for (int i = tid; i < 196 * 16; i += 512) {
        int px = i >> 4, v = i & 15;
        int hy = px / 14, hx = px - hy * 14;
        int gy = y0 + hy, gx = x0 + hx;
        float4 val = make_float4(0.f, 0.f, 0.f, 0.f);
        if (gy >= 0 && gy < HH && gx >= 0 && gx < WW)
            val = *(const float4*)(g_pre + ((size_t)(b * HWSZ + gy * WW + gx)) * 96 + 32 + v * 4);
        *(float4*)(sm + OFF_KV + px * 64 + v * 4) = val;
    }
    for (int i = tid; i < 100 * 8; i += 512) {
        int px = i >> 3, v = i & 7;
        int hy = px / 10, hx = px - hy * 10;
        int gy = y0 + 2 + hy, gx = x0 + 2 + hx;
        float4 val = make_float4(0.f, 0.f, 0.f, 0.f);
        if (gy >= 0 && gy < HH && gx >= 0 && gx < WW)
            val = *(const float4*)(g_pre + ((size_t)(b * HWSZ + gy * WW + gx)) * 96 + v * 4);
        *(float4*)(sm + OFF_QT + px * 32 + v * 4) = val;
    }
    __syncthreads();

    // dw7 all experts: thread = (ch 0..63, row 0..7)
    {
        int ch = tid & 63, row = tid >> 6;
        float acc[4][8];
        #pragma unroll
        for (int e = 0; e < 4; e++) {
            float bv = sm[OFF_B7 + e * 64 + ch];
            #pragma unroll
            for (int j = 0; j < 8; j++) acc[e][j] = bv;
        }
        #pragma unroll
        for (int ky = 0; ky < 7; ky++) {
            const float* inr = sm + OFF_KV + (row + ky) * 896 + ch;
            const int*   owr = sIdx + (row + ky) * 14;
            float in[14]; int ow[14];
            #pragma unroll
            for (int xx = 0; xx < 14; xx++) { in[xx] = inr[xx * 64]; ow[xx] = owr[xx]; }
            #pragma unroll
            for (int e = 0; e < 4; e++) {
                float me[14];
                #pragma unroll
                for (int xx = 0; xx < 14; xx++) me[xx] = (ow[xx] == e) ? in[xx] : 0.f;
                const float* wr = sm + OFF_W7 + (e * 64 + ch) * 49 + ky * 7;
                #pragma unroll
                for (int kx = 0; kx < 7; kx++) {
                    float w = wr[kx];
                    #pragma unroll
                    for (int j = 0; j < 8; j++) acc[e][j] += w * me[j + kx];
                }
            }
        }
        if (ch < 32) {
            #pragma unroll
            for (int e = 0; e < 4; e++) {
                float* kd = sm + OFF_KE + e * ESTRIDE + ch * 65 + row * 8;
                #pragma unroll
                for (int j = 0; j < 8; j++) kd[j] = acc[e][j];
            }
        } else {
            #pragma unroll
            for (int j = 0; j < 8; j++) {
                int own = sIdx[(row + 3) * 14 + (j + 3)];
                float v = (own == 0) ? acc[0][j] : (own == 1) ? acc[1][j]
                        : (own == 2) ? acc[2][j] : acc[3][j];
                sm[OFF_OUT + (row * 8 + j) * 68 + ch] = v;
            }
        }
    }

    // dw3 all experts: threads 0..255 = (ch 0..31, row 0..7)
    if (tid < 256) {
        int ch = tid & 31, row = tid >> 5;
        float acc[4][8];
        #pragma unroll
        for (int e = 0; e < 4; e++) {
            float bv = sm[OFF_B3 + e * 32 + ch];
            #pragma unroll
            for (int j = 0; j < 8; j++) acc[e][j] = bv;
        }
        #pragma unroll
        for (int ky = 0; ky < 3; ky++) {
            const float* inr = sm + OFF_QT + (row + ky) * 320 + ch;
            const int*   owr = sIdx + (row + ky + 2) * 14 + 2;
            float in[10]; int ow[10];
            #pragma unroll
            for (int xx = 0; xx < 10; xx++) { in[xx] = inr[xx * 32]; ow[xx] = owr[xx]; }
            #pragma unroll
            for (int e = 0; e < 4; e++) {
                float me[10];
                #pragma unroll
                for (int xx = 0; xx < 10; xx++) me[xx] = (ow[xx] == e) ? in[xx] : 0.f;
                const float* wr = sm + OFF_W3 + (e * 32 + ch) * 9 + ky * 3;
                #pragma unroll
                for (int kx = 0; kx < 3; kx++) {
                    float w = wr[kx];
                    #pragma unroll
                    for (int j = 0; j < 8; j++) acc[e][j] += w * me[j + kx];
                }
            }
        }
        #pragma unroll
        for (int e = 0; e < 4; e++) {
            float* qd = sm + OFF_QE + e * ESTRIDE + ch * 65 + row * 8;
            #pragma unroll
            for (int j = 0; j < 8; j++) qd[j] = acc[e][j];
        }
    }
    __syncthreads();

    // circular conv per pixel with owner's q,k
    {
        int ch = tid >> 4;
        int g4 = (tid & 15) * 4;
        #pragma unroll
        for (int pp = 0; pp < 4; pp++) {
            int px = g4 + pp;
            int i = px >> 3, j = px & 7;
            int e = sIdx[(i + 3) * 14 + (j + 3)];
            const float* q = sm + OFF_QE + e * ESTRIDE + ch * 65;
            const float* k = sm + OFF_KE + e * ESTRIDE + ch * 65;
            float out = 0.f;
            #pragma unroll
            for (int a = 0; a < 8; a++) {
                const float* qa = q + a * 8;
                const float* ka = k + ((i - a) & 7) * 8;
                #pragma unroll
                for (int bb = 0; bb < 8; bb++)
                    out += qa[bb] * ka[(j - bb) & 7];
            }
            sm[OFF_OUT + px * 68 + ch] = out;
        }
    }
    __syncthreads();

    for (int i = tid; i < 64 * 16; i += 512) {
        int px = i >> 4, v = i & 15;
        int gi = px >> 3, gj = px & 7;
        size_t gp = (size_t)b * HWSZ + (ph * 8 + gi) * WW + (pw * 8 + gj);
        *(float4*)(g_av + gp * 64 + v * 4) = *(float4*)(sm + OFF_OUT + px * 68 + v * 4);
    }
}

// ---------------- DO: LN, *v, fp, silu gate, W2e, +ox ----------------
// per-expert 5216: fp 1024 | p1 2048 | W2 2048 | fpb 32 | lnw 32 | lnb 32
#define DO_OB   20864       // 64
#define DO_SMEM 20928
__global__ __launch_bounds__(256) void k_DO(const float* __restrict__ sh,
                                            const float* __restrict__ fpw,
                                            const float* __restrict__ fpb,
                                            const float* __restrict__ p1w,
                                            const float* __restrict__ lnw,
                                            const float* __restrict__ lnb,
                                            const float* __restrict__ ob,
                                            float* __restrict__ out) {
    extern __shared__ float smd[];
    int tid = threadIdx.x;
    for (int i = tid; i < 4096; i += 256) smd[(i >> 10) * 5216 + (i & 1023)] = fpw[i];
    for (int i = tid; i < 8192; i += 256) smd[(i >> 11) * 5216 + 1024 + (i & 2047)] = p1w[i];
    for (int i = tid; i < 8192; i += 256) smd[(i >> 11) * 5216 + 3072 + (i & 2047)] = g_W2[i];
    if (tid < 128) {
        smd[(tid >> 5) * 5216 + 5120 + (tid & 31)] = fpb[tid];
        smd[(tid >> 5) * 5216 + 5152 + (tid & 31)] = lnw[tid];
        smd[(tid >> 5) * 5216 + 5184 + (tid & 31)] = lnb[tid];
    }
    if (tid < 64) smd[DO_OB + tid] = ob[tid];
    __syncthreads();

    int p = blockIdx.x * 256 + tid;
    int b = p >> 16, s = p & 0xFFFF;
    int e = g_idx[p];
    float m = g_gate[p];
    const float* base_ = smd + e * 5216;
    const float* s_fp  = base_;
    const float* s_p1  = base_ + 1024;
    const float* s_W2  = base_ + 3072;
    const float* s_fpb = base_ + 5120;
    const float* s_lnw = base_ + 5152;
    const float* s_lnb = base_ + 5184;

    // 1. gate dots from shared path
    float gg[32];
    {
        float shv[64];
        const float* shb = sh + ((size_t)b * DIM) * HWSZ + s;
        #pragma unroll
        for (int c = 0; c < 64; c++) shv[c] = shb[(size_t)c * HWSZ];
        #pragma unroll 2
        for (int o = 0; o < 32; o++) {
            const float4* pr = (const float4*)(s_p1 + o * 64);
            float g = 0.f;
            #pragma unroll
            for (int j = 0; j < 16; j++) {
                float4 w = pr[j];
                g += w.x * shv[4*j] + w.y * shv[4*j+1] + w.z * shv[4*j+2] + w.w * shv[4*j+3];
            }
            gg[o] = g;
        }
    }

    // 2. LN(attn) * v
    const float* av = g_av + (size_t)p * 64;
    float t[32], vv[32];
    #pragma unroll
    for (int j = 0; j < 8; j++) {
        float4 a4 = *(const float4*)(av + j * 4);
        t[4*j] = a4.x; t[4*j+1] = a4.y; t[4*j+2] = a4.z; t[4*j+3] = a4.w;
        float4 v4 = *(const float4*)(av + 32 + j * 4);
        vv[4*j] = v4.x; vv[4*j+1] = v4.y; vv[4*j+2] = v4.z; vv[4*j+3] = v4.w;
    }
    float sum = 0.f, sq = 0.f;
    #pragma unroll
    for (int r = 0; r < 32; r++) { sum += t[r]; sq += t[r] * t[r]; }
    float mean = sum * (1.f / 32.f);
    float var  = sq * (1.f / 32.f) - mean * mean;
    float inv  = rsqrtf(var + 1e-5f);
    #pragma unroll
    for (int r = 0; r < 32; r++)
        t[r] = ((t[r] - mean) * inv * s_lnw[r] + s_lnb[r]) * vv[r];

    // 3. body * silu gate
    float bg[32];
    #pragma unroll 2
    for (int o = 0; o < 32; o++) {
        const float4* fr = (const float4*)(s_fp + o * 32);
        float acc = s_fpb[o];
        #pragma unroll
        for (int j = 0; j < 8; j++) {
            float4 w = fr[j];
            acc += w.x * t[4*j] + w.y * t[4*j+1] + w.z * t[4*j+2] + w.w * t[4*j+3];
        }
        float z = m * gg[o];
        float sg = z / (1.f + expf(-z));
        bg[o] = acc * sg;
    }

    // 4. out = m*(W2e@bg) + m^2*ox + outb
    float oxv[64];
    const float* oxp = g_ox + (size_t)p * 64;
    #pragma unroll
    for (int j = 0; j < 16; j++) {
        float4 o4 = *(const float4*)(oxp + j * 4);
        oxv[4*j] = o4.x; oxv[4*j+1] = o4.y; oxv[4*j+2] = o4.z; oxv[4*j+3] = o4.w;
    }
    float m2 = m * m;
    float* ob_ = out + ((size_t)b * DIM) * HWSZ + s;
    #pragma unroll 2
    for (int o = 0; o < 64; o++) {
        const float4* wr = (const float4*)(s_W2 + o * 32);
        float acc = 0.f;
        #pragma unroll
        for (int j = 0; j < 8; j++) {
            float4 w = wr[j];
            acc += w.x * bg[4*j] + w.y * bg[4*j+1] + w.z * bg[4*j+2] + w.w * bg[4*j+3];
        }
        ob_[(size_t)o * HWSZ] = m * acc + m2 * oxv[o] + smd[DO_OB + o];
    }
}

// ---------------- launch ----------------
extern "C" void kernel_launch(void* const* d_in, const int* in_sizes, int n_in,
                              void* d_out, int out_size) {
    const float* x     = (const float*)d_in[0];
    const float* sh    = (const float*)d_in[1];
    const float* rw    = (const float*)d_in[2];
    const float* rb    = (const float*)d_in[3];
    const float* p0w   = (const float*)d_in[4];
    const float* p1w   = (const float*)d_in[5];
    const float* p2w   = (const float*)d_in[6];
    const float* qw    = (const float*)d_in[7];
    const float* qdww  = (const float*)d_in[8];
    const float* qdwb  = (const float*)d_in[9];
    const float* kvw   = (const float*)d_in[10];
    const float* kvdww = (const float*)d_in[11];
    const float* kvdwb = (const float*)d_in[12];
    const float* lnw   = (const float*)d_in[13];
    const float* lnb   = (const float*)d_in[14];
    const float* fpw   = (const float*)d_in[15];
    const float* fpb   = (const float*)d_in[16];
    const float* outw  = (const float*)d_in[17];
    const float* outb  = (const float*)d_in[18];
    float* out = (float*)d_out;

    static int inited = 0;
    if (!inited) {
        cudaFuncSetAttribute(k_AR, cudaFuncAttributeMaxDynamicSharedMemorySize, 24836 * 4);
        cudaFuncSetAttribute(k_B,  cudaFuncAttributeMaxDynamicSharedMemorySize, SMEM_B_FLOATS * 4);
        cudaFuncSetAttribute(k_DO, cudaFuncAttributeMaxDynamicSharedMemorySize, DO_SMEM * 4);
        inited = 1;
    }

    k_prep<<<128, 256>>>(qw, kvw, p0w, p2w, outw);
    k_AR<<<NPIX / 256, 256, 24836 * 4>>>(x, rw, rb);
    k_OX<<<NPIX / 256, 256>>>(x, outw);
    k_B<<<BB * 1024, 512, SMEM_B_FLOATS * 4>>>(qdww, qdwb, kvdww, kvdwb);
    k_DO<<<NPIX / 256, 256, DO_SMEM * 4>>>(sh, fpw, fpb, p1w, lnw, lnb, outb, out);
}

// round 8
// speedup vs baseline: 1.0629x; 1.0629x over previous
#include <cuda_runtime.h>

// ---------------- problem constants ----------------
#define BB    4
#define DIM   64
#define RANK  32
#define EE    4
#define HH    256
#define WW    256
#define HWSZ  65536
#define NPIX  262144

// ---------------- device scratch ----------------
__device__ float g_gate[NPIX];
__device__ int   g_idx[NPIX];
__device__ float g_W[4 * 96 * 64];           // fused [Wq;Wkv] per expert
__device__ float g_W2[4 * 64 * 32];          // ow @ p2w per expert
__device__ float g_pre[(size_t)NPIX * 96];   // [p][0:32)=qpre, [32:96)=kvpre
__device__ float g_av [(size_t)NPIX * 64];   // [p][0:32)=attn, [32:64)=v

// ---------------- prep: fold weight products ----------------
__global__ void k_prep(const float* __restrict__ qw,
                       const float* __restrict__ kvw,
                       const float* __restrict__ p0,
                       const float* __restrict__ p2w,
                       const float* __restrict__ ow) {
    int i = blockIdx.x * blockDim.x + threadIdx.x;     // < 32768
    if (i < 24576) {
        int e = i / 6144;
        int rem = i - e * 6144;
        int o = rem >> 6, c = rem & 63;
        const float* p0e = p0 + e * 2048;
        float acc = 0.f;
        if (o < 32) {
            const float* qe = qw + e * 1024 + o * 32;
            #pragma unroll
            for (int r = 0; r < 32; r++) acc += qe[r] * p0e[r * 64 + c];
        } else {
            const float* ke = kvw + e * 2048 + (o - 32) * 32;
            #pragma unroll
            for (int r = 0; r < 32; r++) acc += ke[r] * p0e[r * 64 + c];
        }
        g_W[i] = acc;
    } else {
        int j = i - 24576;                             // < 8192
        int e = j >> 11;
        int rem = j & 2047;
        int o = rem >> 5, r = rem & 31;
        const float* p2e = p2w + e * 2048;
        const float* owr = ow + o * 64;
        float acc = 0.f;
        #pragma unroll
        for (int c = 0; c < 64; c++) acc += owr[c] * p2e[c * 32 + r];
        g_W2[e * 2048 + o * 32 + r] = acc;
    }
}

// ---------------- AR: fused router + 1x1 conv -> g_pre ----------------
__global__ __launch_bounds__(256) void k_AR(const float* __restrict__ x,
                                            const float* __restrict__ rw,
                                            const float* __restrict__ rb) {
    extern __shared__ float sW[];     // 24576 W | 256 rw | 4 rb
    int tid = threadIdx.x;
    for (int i = tid; i < 24576; i += 256) sW[i] = g_W[i];
    if (tid < 256) sW[24576 + tid] = rw[tid];
    if (tid < 4)   sW[24832 + tid] = rb[tid];
    __syncthreads();

    int p = blockIdx.x * 256 + tid;
    int b = p >> 16, s = p & 0xFFFF;
    const float* xb = x + ((size_t)b * DIM) * HWSZ + s;
    float xv[64];
    #pragma unroll
    for (int c = 0; c < 64; c++) xv[c] = xb[(size_t)c * HWSZ];

    const float* srw = sW + 24576;
    float l0 = sW[24832], l1 = sW[24833], l2 = sW[24834], l3 = sW[24835];
    #pragma unroll
    for (int c = 0; c < 64; c++) {
        float v = xv[c];
        l0 += srw[c] * v; l1 += srw[64 + c] * v;
        l2 += srw[128 + c] * v; l3 += srw[192 + c] * v;
    }
    float lm = l0; int am = 0;
    if (l1 > lm) { lm = l1; am = 1; }
    if (l2 > lm) { lm = l2; am = 2; }
    if (l3 > lm) { lm = l3; am = 3; }
    float m = 1.0f / (expf(l0 - lm) + expf(l1 - lm) + expf(l2 - lm) + expf(l3 - lm));
    g_gate[p] = m;
    g_idx[p]  = am;

    #pragma unroll
    for (int c = 0; c < 64; c++) xv[c] *= m;

    const float4* Wv = (const float4*)(sW + am * 6144);
    float* op = g_pre + (size_t)p * 96;
    #pragma unroll 2
    for (int og = 0; og < 24; og++) {
        float r[4];
        #pragma unroll
        for (int u = 0; u < 4; u++) {
            const float4* wr = Wv + (og * 4 + u) * 16;
            float acc = 0.f;
            #pragma unroll
            for (int j = 0; j < 16; j++) {
                float4 w = wr[j];
                acc += w.x * xv[4*j] + w.y * xv[4*j+1] + w.z * xv[4*j+2] + w.w * xv[4*j+3];
            }
            r[u] = acc;
        }
        *(float4*)(op + og * 4) = make_float4(r[0], r[1], r[2], r[3]);
    }
}

// ---------------- B: fused masked dwconv(3,7) + patch circular conv ----------------
// expert-presence loop: only experts owning pixels in this patch are computed
#define OFF_KV   0          // 196*64 = 12544
#define OFF_QT   12544      // 100*32 = 3200
#define OFF_QE   15744      // 4*2081
#define OFF_KE   24068      // 4*2081
#define OFF_OUT  32392      // 64*68
#define OFF_W7   36744      // 4*64*49
#define OFF_W3   49288      // 4*32*9
#define OFF_B7   50440      // 256
#define OFF_B3   50696      // 128
#define OFF_IDX  50824      // 196 ints
#define SMEM_B_FLOATS 51020
#define ESTRIDE  2081

__global__ __launch_bounds__(512) void k_B(const float* __restrict__ qdww,
                                           const float* __restrict__ qdwb,
                                           const float* __restrict__ kvdww,
                                           const float* __restrict__ kvdwb) {
    extern __shared__ float sm[];
    int* sIdx = (int*)(sm + OFF_IDX);
    int tid = threadIdx.x;
    int blk = blockIdx.x;
    int b = blk >> 10, sp = blk & 1023, ph = sp >> 5, pw = sp & 31;
    int y0 = ph * 8 - 3, x0 = pw * 8 - 3;

    // ---- halos + owner map ----
    for (int i = tid; i < 196; i += 512) {
        int hy = i / 14, hx = i - hy * 14;
        int gy = y0 + hy, gx = x0 + hx;
        sIdx[i] = (gy >= 0 && gy < HH && gx >= 0 && gx < WW)
                ? g_idx[b * HWSZ + gy * WW + gx] : -1;
    }
    for (int i = tid; i < 196 * 16; i += 512) {
        int px = i >> 4, v = i & 15;
        int hy = px / 14, hx = px - hy * 14;
        int gy = y0 + hy, gx = x0 + hx;
        float4 val = make_float4(0.f, 0.f, 0.f, 0.f);
        if (gy >= 0 && gy < HH && gx >= 0 && gx < WW)
            val = *(const float4*)(g_pre + ((size_t)(b * HWSZ + gy * WW + gx)) * 96 + 32 + v * 4);
        *(float4*)(sm + OFF_KV + px * 64 + v * 4) = val;
    }
    for (int i = tid; i < 100 * 8; i += 512) {
        int px = i >> 3, v = i & 7;
        int hy = px / 10, hx = px - hy * 10;
        int gy = y0 + 2 + hy, gx = x0 + 2 + hx;
        float4 val = make_float4(0.f, 0.f, 0.f, 0.f);
        if (gy >= 0 && gy < HH && gx >= 0 && gx < WW)
            val = *(const float4*)(g_pre + ((size_t)(b * HWSZ + gy * WW + gx)) * 96 + v * 4);
        *(float4*)(sm + OFF_QT + px * 32 + v * 4) = val;
    }
    __syncthreads();

    // ---- which experts own output pixels of this patch? ----
    int bit = 0;
    if (tid < 64) {
        int i = tid >> 3, j = tid & 7;
        bit = 1 << sIdx[(i + 3) * 14 + (j + 3)];
    }
    int mask = __syncthreads_or(bit);

    // ---- stage weights only for present experts ----
    for (int e = 0; e < 4; e++) {
        if (!((mask >> e) & 1)) continue;
        for (int i = tid; i < 3136; i += 512) sm[OFF_W7 + e * 3136 + i] = kvdww[e * 3136 + i];
        if (tid < 288) sm[OFF_W3 + e * 288 + tid] = qdww[e * 288 + tid];
        if (tid < 64)  sm[OFF_B7 + e * 64 + tid]  = kvdwb[e * 64 + tid];
        if (tid < 32)  sm[OFF_B3 + e * 32 + tid]  = qdwb[e * 32 + tid];
    }
    __syncthreads();

    // ---- dw7 per present expert: thread = (ch 0..63, row 0..7) ----
    {
        int ch = tid & 63, row = tid >> 6;
        for (int e = 0; e < 4; e++) {
            if (!((mask >> e) & 1)) continue;
            float bv = sm[OFF_B7 + e * 64 + ch];
            float acc[8];
            #pragma unroll
            for (int j = 0; j < 8; j++) acc[j] = bv;
            #pragma unroll
            for (int ky = 0; ky < 7; ky++) {
                const float* inr = sm + OFF_KV + (row + ky) * 896 + ch;
                const int*   owr = sIdx + (row + ky) * 14;
                float me[14];
                #pragma unroll
                for (int xx = 0; xx < 14; xx++)
                    me[xx] = (owr[xx] == e) ? inr[xx * 64] : 0.f;
                const float* wr = sm + OFF_W7 + (e * 64 + ch) * 49 + ky * 7;
                #pragma unroll
                for (int kx = 0; kx < 7; kx++) {
                    float w = wr[kx];
                    #pragma unroll
                    for (int j = 0; j < 8; j++) acc[j] += w * me[j + kx];
                }
            }
            if (ch < 32) {
                float* kd = sm + OFF_KE + e * ESTRIDE + ch * 65 + row * 8;
                #pragma unroll
                for (int j = 0; j < 8; j++) kd[j] = acc[j];
            } else {
                #pragma unroll
                for (int j = 0; j < 8; j++) {
                    int own = sIdx[(row + 3) * 14 + (j + 3)];
                    if (own == e) sm[OFF_OUT + (row * 8 + j) * 68 + ch] = acc[j];
                }
            }
        }
    }

    // ---- dw3 per present expert: threads 0..255 = (ch 0..31, row 0..7) ----
    if (tid < 256) {
        int ch = tid & 31, row = tid >> 5;
        for (int e = 0; e < 4; e++) {
            if (!((mask >> e) & 1)) continue;
            float bv = sm[OFF_B3 + e * 32 + ch];
            float acc[8];
            #pragma unroll
            for (int j = 0; j < 8; j++) acc[j] = bv;
            #pragma unroll
            for (int ky = 0; ky < 3; ky++) {
                const float* inr = sm + OFF_QT + (row + ky) * 320 + ch;
                const int*   owr = sIdx + (row + ky + 2) * 14 + 2;
                float me[10];
                #pragma unroll
                for (int xx = 0; xx < 10; xx++)
                    me[xx] = (owr[xx] == e) ? inr[xx * 32] : 0.f;
                const float* wr = sm + OFF_W3 + (e * 32 + ch) * 9 + ky * 3;
                #pragma unroll
                for (int kx = 0; kx < 3; kx++) {
                    float w = wr[kx];
                    #pragma unroll
                    for (int j = 0; j < 8; j++) acc[j] += w * me[j + kx];
                }
            }
            float* qd = sm + OFF_QE + e * ESTRIDE + ch * 65 + row * 8;
            #pragma unroll
            for (int j = 0; j < 8; j++) qd[j] = acc[j];
        }
    }
    __syncthreads();

    // ---- circular conv per pixel with owner's q,k ----
    {
        int ch = tid >> 4;
        int g4 = (tid & 15) * 4;
        #pragma unroll
        for (int pp = 0; pp < 4; pp++) {
            int px = g4 + pp;
            int i = px >> 3, j = px & 7;
            int e = sIdx[(i + 3) * 14 + (j + 3)];
            const float* q = sm + OFF_QE + e * ESTRIDE + ch * 65;
            const float* k = sm + OFF_KE + e * ESTRIDE + ch * 65;
            float out = 0.f;
            #pragma unroll
            for (int a = 0; a < 8; a++) {
                const float* qa = q + a * 8;
                const float* ka = k + ((i - a) & 7) * 8;
                #pragma unroll
                for (int bb = 0; bb < 8; bb++)
                    out += qa[bb] * ka[(j - bb) & 7];
            }
            sm[OFF_OUT + px * 68 + ch] = out;
        }
    }
    __syncthreads();

    for (int i = tid; i < 64 * 16; i += 512) {
        int px = i >> 4, v = i & 15;
        int gi = px >> 3, gj = px & 7;
        size_t gp = (size_t)b * HWSZ + (ph * 8 + gi) * WW + (pw * 8 + gj);
        *(float4*)(g_av + gp * 64 + v * 4) = *(float4*)(sm + OFF_OUT + px * 68 + v * 4);
    }
}

// ---------------- DO: LN, *v, fp, silu gate, W2e, ow@x inline ----------------
// per-expert 5216: fp 1024 | p1 2048 | W2 2048 | fpb 32 | lnw 32 | lnb 32
#define DO_OB   20864       // 64
#define DO_OW   20928       // 4096
#define DO_SMEM 25024
__global__ __launch_bounds__(256) void k_DO(const float* __restrict__ x,
                                            const float* __restrict__ sh,
                                            const float* __restrict__ fpw,
                                            const float* __restrict__ fpb,
                                            const float* __restrict__ p1w,
                                            const float* __restrict__ lnw,
                                            const float* __restrict__ lnb,
                                            const float* __restrict__ ow,
                                            const float* __restrict__ ob,
                                            float* __restrict__ out) {
    extern __shared__ float smd[];
    int tid = threadIdx.x;
    for (int i = tid; i < 4096; i += 256) smd[(i >> 10) * 5216 + (i & 1023)] = fpw[i];
    for (int i = tid; i < 8192; i += 256) smd[(i >> 11) * 5216 + 1024 + (i & 2047)] = p1w[i];
    for (int i = tid; i < 8192; i += 256) smd[(i >> 11) * 5216 + 3072 + (i & 2047)] = g_W2[i];
    if (tid < 128) {
        smd[(tid >> 5) * 5216 + 5120 + (tid & 31)] = fpb[tid];
        smd[(tid >> 5) * 5216 + 5152 + (tid & 31)] = lnw[tid];
        smd[(tid >> 5) * 5216 + 5184 + (tid & 31)] = lnb[tid];
    }
    for (int i = tid; i < 4096; i += 256) smd[DO_OW + i] = ow[i];
    if (tid < 64) smd[DO_OB + tid] = ob[tid];
    __syncthreads();

    int p = blockIdx.x * 256 + tid;
    int b = p >> 16, s = p & 0xFFFF;
    int e = g_idx[p];
    float m = g_gate[p];
    const float* base_ = smd + e * 5216;
    const float* s_fp  = base_;
    const float* s_p1  = base_ + 1024;
    const float* s_W2  = base_ + 3072;
    const float* s_fpb = base_ + 5120;
    const float* s_lnw = base_ + 5152;
    const float* s_lnb = base_ + 5184;

    // 1. gate dots from shared path
    float gg[32];
    {
        float shv[64];
        const float* shb = sh + ((size_t)b * DIM) * HWSZ + s;
        #pragma unroll
        for (int c = 0; c < 64; c++) shv[c] = shb[(size_t)c * HWSZ];
        #pragma unroll 2
        for (int o = 0; o < 32; o++) {
            const float4* pr = (const float4*)(s_p1 + o * 64);
            float g = 0.f;
            #pragma unroll
            for (int j = 0; j < 16; j++) {
                float4 w = pr[j];
                g += w.x * shv[4*j] + w.y * shv[4*j+1] + w.z * shv[4*j+2] + w.w * shv[4*j+3];
            }
            gg[o] = g;
        }
    }

    // 2. LN(attn) * v
    const float* av = g_av + (size_t)p * 64;
    float t[32], vv[32];
    #pragma unroll
    for (int j = 0; j < 8; j++) {
        float4 a4 = *(const float4*)(av + j * 4);
        t[4*j] = a4.x; t[4*j+1] = a4.y; t[4*j+2] = a4.z; t[4*j+3] = a4.w;
        float4 v4 = *(const float4*)(av + 32 + j * 4);
        vv[4*j] = v4.x; vv[4*j+1] = v4.y; vv[4*j+2] = v4.z; vv[4*j+3] = v4.w;
    }
    float sum = 0.f, sq = 0.f;
    #pragma unroll
    for (int r = 0; r < 32; r++) { sum += t[r]; sq += t[r] * t[r]; }
    float mean = sum * (1.f / 32.f);
    float var  = sq * (1.f / 32.f) - mean * mean;
    float inv  = rsqrtf(var + 1e-5f);
    #pragma unroll
    for (int r = 0; r < 32; r++)
        t[r] = ((t[r] - mean) * inv * s_lnw[r] + s_lnb[r]) * vv[r];

    // 3. body * silu gate
    float bg[32];
    #pragma unroll 2
    for (int o = 0; o < 32; o++) {
        const float4* fr = (const float4*)(s_fp + o * 32);
        float acc = s_fpb[o];
        #pragma unroll
        for (int j = 0; j < 8; j++) {
            float4 w = fr[j];
            acc += w.x * t[4*j] + w.y * t[4*j+1] + w.z * t[4*j+2] + w.w * t[4*j+3];
        }
        float z = m * gg[o];
        float sg = z / (1.f + expf(-z));
        bg[o] = acc * sg;
    }

    // 4. out = m*(W2e@bg) + m^2*(ow@x) + outb
    float xv[64];
    const float* xb = x + ((size_t)b * DIM) * HWSZ + s;
    #pragma unroll
    for (int c = 0; c < 64; c++) xv[c] = xb[(size_t)c * HWSZ];
    float m2 = m * m;
    float* ob_ = out + ((size_t)b * DIM) * HWSZ + s;
    #pragma unroll 1
    for (int o = 0; o < 64; o++) {
        const float4* wr = (const float4*)(s_W2 + o * 32);
        float acc = 0.f;
        #pragma unroll
        for (int j = 0; j < 8; j++) {
            float4 w = wr[j];
            acc += w.x * bg[4*j] + w.y * bg[4*j+1] + w.z * bg[4*j+2] + w.w * bg[4*j+3];
        }
        const float4* owr = (const float4*)(smd + DO_OW + o * 64);
        float oxo = 0.f;
        #pragma unroll
        for (int j = 0; j < 16; j++) {
            float4 w = owr[j];
            oxo += w.x * xv[4*j] + w.y * xv[4*j+1] + w.z * xv[4*j+2] + w.w * xv[4*j+3];
        }
        ob_[(size_t)o * HWSZ] = m * acc + m2 * oxo + smd[DO_OB + o];
    }
}

// ---------------- launch ----------------
extern "C" void kernel_launch(void* const* d_in, const int* in_sizes, int n_in,
                              void* d_out, int out_size) {
    const float* x     = (const float*)d_in[0];
    const float* sh    = (const float*)d_in[1];
    const float* rw    = (const float*)d_in[2];
    const float* rb    = (const float*)d_in[3];
    const float* p0w   = (const float*)d_in[4];
    const float* p1w   = (const float*)d_in[5];
    const float* p2w   = (const float*)d_in[6];
    const float* qw    = (const float*)d_in[7];
    const float* qdww  = (const float*)d_in[8];
    const float* qdwb  = (const float*)d_in[9];
    const float* kvw   = (const float*)d_in[10];
    const float* kvdww = (const float*)d_in[11];
    const float* kvdwb = (const float*)d_in[12];
    const float* lnw   = (const float*)d_in[13];
    const float* lnb   = (const float*)d_in[14];
    const float* fpw   = (const float*)d_in[15];
    const float* fpb   = (const float*)d_in[16];
    const float* outw  = (const float*)d_in[17];
    const float* outb  = (const float*)d_in[18];
    float* out = (float*)d_out;

    static int inited = 0;
    if (!inited) {
        cudaFuncSetAttribute(k_AR, cudaFuncAttributeMaxDynamicSharedMemorySize, 24836 * 4);
        cudaFuncSetAttribute(k_B,  cudaFuncAttributeMaxDynamicSharedMemorySize, SMEM_B_FLOATS * 4);
        cudaFuncSetAttribute(k_DO, cudaFuncAttributeMaxDynamicSharedMemorySize, DO_SMEM * 4);
        inited = 1;
    }

    k_prep<<<128, 256>>>(qw, kvw, p0w, p2w, outw);
    k_AR<<<NPIX / 256, 256, 24836 * 4>>>(x, rw, rb);
    k_B<<<BB * 1024, 512, SMEM_B_FLOATS * 4>>>(qdww, qdwb, kvdww, kvdwb);
    k_DO<<<NPIX / 256, 256, DO_SMEM * 4>>>(x, sh, fpw, fpb, p1w, lnw, lnb,
                                           outw, outb, out);
}

// round 10
// speedup vs baseline: 1.0713x; 1.0079x over previous
#include <cuda_runtime.h>

// ---------------- problem constants ----------------
#define BB    4
#define DIM   64
#define RANK  32
#define EE    4
#define HH    256
#define WW    256
#define HWSZ  65536
#define NPIX  262144

// ---------------- device scratch ----------------
__device__ float g_gate[NPIX];
__device__ int   g_idx[NPIX];
__device__ float g_W[4 * 96 * 64];           // fused [Wq;Wkv] per expert
__device__ float g_W2[4 * 64 * 32];          // ow @ p2w per expert
__device__ float g_pre[(size_t)NPIX * 96];   // [p][0:32)=qpre, [32:96)=kvpre
__device__ float g_av [(size_t)NPIX * 64];   // [p][0:32)=attn, [32:64)=v
__device__ float g_ox [(size_t)NPIX * 64];   // m^2*(ow@x) + outb, pixel-major

// ---------------- prep: fold weight products ----------------
__global__ void k_prep(const float* __restrict__ qw,
                       const float* __restrict__ kvw,
                       const float* __restrict__ p0,
                       const float* __restrict__ p2w,
                       const float* __restrict__ ow) {
    int i = blockIdx.x * blockDim.x + threadIdx.x;     // < 32768
    if (i < 24576) {
        int e = i / 6144;
        int rem = i - e * 6144;
        int o = rem >> 6, c = rem & 63;
        const float* p0e = p0 + e * 2048;
        float acc = 0.f;
        if (o < 32) {
            const float* qe = qw + e * 1024 + o * 32;
            #pragma unroll
            for (int r = 0; r < 32; r++) acc += qe[r] * p0e[r * 64 + c];
        } else {
            const float* ke = kvw + e * 2048 + (o - 32) * 32;
            #pragma unroll
            for (int r = 0; r < 32; r++) acc += ke[r] * p0e[r * 64 + c];
        }
        g_W[i] = acc;
    } else {
        int j = i - 24576;                             // < 8192
        int e = j >> 11;
        int rem = j & 2047;
        int o = rem >> 5, r = rem & 31;
        const float* p2e = p2w + e * 2048;
        const float* owr = ow + o * 64;
        float acc = 0.f;
        #pragma unroll
        for (int c = 0; c < 64; c++) acc += owr[c] * p2e[c * 32 + r];
        g_W2[e * 2048 + o * 32 + r] = acc;
    }
}

// ---------------- AR: router + 1x1 conv + ow@x -> g_pre, g_ox ----------------
// sW: [0,24576) W | rw 24576 | rb 24832 | ow 24836 | outb 28932 ; total 28996
#define AR_SMEM 28996
__global__ __launch_bounds__(256) void k_AR(const float* __restrict__ x,
                                            const float* __restrict__ rw,
                                            const float* __restrict__ rb,
                                            const float* __restrict__ ow,
                                            const float* __restrict__ ob) {
    extern __shared__ float sW[];
    int tid = threadIdx.x;
    for (int i = tid; i < 24576; i += 256) sW[i] = g_W[i];
    if (tid < 256) sW[24576 + tid] = rw[tid];
    if (tid < 4)   sW[24832 + tid] = rb[tid];
    for (int i = tid; i < 4096; i += 256) sW[24836 + i] = ow[i];
    if (tid < 64)  sW[28932 + tid] = ob[tid];
    __syncthreads();

    int p = blockIdx.x * 256 + tid;
    int b = p >> 16, s = p & 0xFFFF;
    const float* xb = x + ((size_t)b * DIM) * HWSZ + s;
    float xv[64];
    #pragma unroll
    for (int c = 0; c < 64; c++) xv[c] = xb[(size_t)c * HWSZ];

    const float* srw = sW + 24576;
    float l0 = sW[24832], l1 = sW[24833], l2 = sW[24834], l3 = sW[24835];
    #pragma unroll
    for (int c = 0; c < 64; c++) {
        float v = xv[c];
        l0 += srw[c] * v; l1 += srw[64 + c] * v;
        l2 += srw[128 + c] * v; l3 += srw[192 + c] * v;
    }
    float lm = l0; int am = 0;
    if (l1 > lm) { lm = l1; am = 1; }
    if (l2 > lm) { lm = l2; am = 2; }
    if (l3 > lm) { lm = l3; am = 3; }
    float m = 1.0f / (expf(l0 - lm) + expf(l1 - lm) + expf(l2 - lm) + expf(l3 - lm));
    g_gate[p] = m;
    g_idx[p]  = am;

    #pragma unroll
    for (int c = 0; c < 64; c++) xv[c] *= m;      // xv = m*x

    // qpre/kvpre with owner's fused W
    const float4* Wv = (const float4*)(sW + am * 6144);
    float* op = g_pre + (size_t)p * 96;
    #pragma unroll 2
    for (int og = 0; og < 24; og++) {
        float r[4];
        #pragma unroll
        for (int u = 0; u < 4; u++) {
            const float4* wr = Wv + (og * 4 + u) * 16;
            float acc = 0.f;
            #pragma unroll
            for (int j = 0; j < 16; j++) {
                float4 w = wr[j];
                acc += w.x * xv[4*j] + w.y * xv[4*j+1] + w.z * xv[4*j+2] + w.w * xv[4*j+3];
            }
            r[u] = acc;
        }
        *(float4*)(op + og * 4) = make_float4(r[0], r[1], r[2], r[3]);
    }

    // g_ox = m*(ow @ (m*x)) + outb  == m^2*(ow@x)+outb
    float* oxp = g_ox + (size_t)p * 64;
    #pragma unroll 2
    for (int og = 0; og < 16; og++) {
        float r[4];
        #pragma unroll
        for (int u = 0; u < 4; u++) {
            int o = og * 4 + u;
            const float4* wr = (const float4*)(sW + 24836 + o * 64);
            float acc = 0.f;
            #pragma unroll
            for (int j = 0; j < 16; j++) {
                float4 w = wr[j];
                acc += w.x * xv[4*j] + w.y * xv[4*j+1] + w.z * xv[4*j+2] + w.w * xv[4*j+3];
            }
            r[u] = m * acc + sW[28932 + o];
        }
        *(float4*)(oxp + og * 4) = make_float4(r[0], r[1], r[2], r[3]);
    }
}

// ---------------- B: fused masked dwconv(3,7) + patch circular conv ----------------
// (byte-identical logic to the R8 passing version)
#define OFF_KV   0          // 196*64 = 12544
#define OFF_QT   12544      // 100*32 = 3200
#define OFF_QE   15744      // 4*2081
#define OFF_KE   24068      // 4*2081
#define OFF_OUT  32392      // 64*68
#define OFF_W7   36744      // 4*64*49
#define OFF_W3   49288      // 4*32*9
#define OFF_B7   50440      // 256
#define OFF_B3   50696      // 128
#define OFF_IDX  50824      // 196 ints
#define SMEM_B_FLOATS 51020
#define ESTRIDE  2081

__global__ __launch_bounds__(512) void k_B(const float* __restrict__ qdww,
                                           const float* __restrict__ qdwb,
                                           const float* __restrict__ kvdww,
                                           const float* __restrict__ kvdwb) {
    extern __shared__ float sm[];
    int* sIdx = (int*)(sm + OFF_IDX);
    int tid = threadIdx.x;
    int blk = blockIdx.x;
    int b = blk >> 10, sp = blk & 1023, ph = sp >> 5, pw = sp & 31;
    int y0 = ph * 8 - 3, x0 = pw * 8 - 3;

    // ---- halos + owner map ----
    for (int i = tid; i < 196; i += 512) {
        int hy = i / 14, hx = i - hy * 14;
        int gy = y0 + hy, gx = x0 + hx;
        sIdx[i] = (gy >= 0 && gy < HH && gx >= 0 && gx < WW)
                ? g_idx[b * HWSZ + gy * WW + gx] : -1;
    }
    for (int i = tid; i < 196 * 16; i += 512) {
        int px = i >> 4, v = i & 15;
        int hy = px / 14, hx = px - hy * 14;
        int gy = y0 + hy, gx = x0 + hx;
        float4 val = make_float4(0.f, 0.f, 0.f, 0.f);
        if (gy >= 0 && gy < HH && gx >= 0 && gx < WW)
            val = *(const float4*)(g_pre + ((size_t)(b * HWSZ + gy * WW + gx)) * 96 + 32 + v * 4);
        *(float4*)(sm + OFF_KV + px * 64 + v * 4) = val;
    }
    for (int i = tid; i < 100 * 8; i += 512) {
        int px = i >> 3, v = i & 7;
        int hy = px / 10, hx = px - hy * 10;
        int gy = y0 + 2 + hy, gx = x0 + 2 + hx;
        float4 val = make_float4(0.f, 0.f, 0.f, 0.f);
        if (gy >= 0 && gy < HH && gx >= 0 && gx < WW)
            val = *(const float4*)(g_pre + ((size_t)(b * HWSZ + gy * WW + gx)) * 96 + v * 4);
        *(float4*)(sm + OFF_QT + px * 32 + v * 4) = val;
    }
    __syncthreads();

    // ---- expert presence ----
    int bit = 0;
    if (tid < 64) {
        int i = tid >> 3, j = tid & 7;
        bit = 1 << sIdx[(i + 3) * 14 + (j + 3)];
    }
    int mask = __syncthreads_or(bit);

    // ---- stage dw weights for present experts ----
    for (int e = 0; e < 4; e++) {
        if (!((mask >> e) & 1)) continue;
        for (int i = tid; i < 3136; i += 512) sm[OFF_W7 + e * 3136 + i] = kvdww[e * 3136 + i];
        if (tid < 288) sm[OFF_W3 + e * 288 + tid] = qdww[e * 288 + tid];
        if (tid < 64)  sm[OFF_B7 + e * 64 + tid]  = kvdwb[e * 64 + tid];
        if (tid < 32)  sm[OFF_B3 + e * 32 + tid]  = qdwb[e * 32 + tid];
    }
    __syncthreads();

    // ---- dw7 per present expert ----
    {
        int ch = tid & 63, row = tid >> 6;
        for (int e = 0; e < 4; e++) {
            if (!((mask >> e) & 1)) continue;
            float bv = sm[OFF_B7 + e * 64 + ch];
            float acc[8];
            #pragma unroll
            for (int j = 0; j < 8; j++) acc[j] = bv;
            #pragma unroll
            for (int ky = 0; ky < 7; ky++) {
                const float* inr = sm + OFF_KV + (row + ky) * 896 + ch;
                const int*   owr = sIdx + (row + ky) * 14;
                float me[14];
                #pragma unroll
                for (int xx = 0; xx < 14; xx++)
                    me[xx] = (owr[xx] == e) ? inr[xx * 64] : 0.f;
                const float* wr = sm + OFF_W7 + (e * 64 + ch) * 49 + ky * 7;
                #pragma unroll
                for (int kx = 0; kx < 7; kx++) {
                    float w = wr[kx];
                    #pragma unroll
                    for (int j = 0; j < 8; j++) acc[j] += w * me[j + kx];
                }
            }
            if (ch < 32) {
                float* kd = sm + OFF_KE + e * ESTRIDE + ch * 65 + row * 8;
                #pragma unroll
                for (int j = 0; j < 8; j++) kd[j] = acc[j];
            } else {
                #pragma unroll
                for (int j = 0; j < 8; j++) {
                    int own = sIdx[(row + 3) * 14 + (j + 3)];
                    if (own == e) sm[OFF_OUT + (row * 8 + j) * 68 + ch] = acc[j];
                }
            }
        }
    }

    // ---- dw3 per present expert ----
    if (tid < 256) {
        int ch = tid & 31, row = tid >> 5;
        for (int e = 0; e < 4; e++) {
            if (!((mask >> e) & 1)) continue;
            float bv = sm[OFF_B3 + e * 32 + ch];
            float acc[8];
            #pragma unroll
            for (int j = 0; j < 8; j++) acc[j] = bv;
            #pragma unroll
            for (int ky = 0; ky < 3; ky++) {
                const float* inr = sm + OFF_QT + (row + ky) * 320 + ch;
                const int*   owr = sIdx + (row + ky + 2) * 14 + 2;
                float me[10];
                #pragma unroll
                for (int xx = 0; xx < 10; xx++)
                    me[xx] = (owr[xx] == e) ? inr[xx * 32] : 0.f;
                const float* wr = sm + OFF_W3 + (e * 32 + ch) * 9 + ky * 3;
                #pragma unroll
                for (int kx = 0; kx < 3; kx++) {
                    float w = wr[kx];
                    #pragma unroll
                    for (int j = 0; j < 8; j++) acc[j] += w * me[j + kx];
                }
            }
            float* qd = sm + OFF_QE + e * ESTRIDE + ch * 65 + row * 8;
            #pragma unroll
            for (int j = 0; j < 8; j++) qd[j] = acc[j];
        }
    }
    __syncthreads();

    // ---- circular conv per pixel with owner's q,k ----
    {
        int ch = tid >> 4;
        int g4 = (tid & 15) * 4;
        #pragma unroll
        for (int pp = 0; pp < 4; pp++) {
            int px = g4 + pp;
            int i = px >> 3, j = px & 7;
            int e = sIdx[(i + 3) * 14 + (j + 3)];
            const float* q = sm + OFF_QE + e * ESTRIDE + ch * 65;
            const float* k = sm + OFF_KE + e * ESTRIDE + ch * 65;
            float o = 0.f;
            #pragma unroll
            for (int a = 0; a < 8; a++) {
                const float* qa = q + a * 8;
                const float* ka = k + ((i - a) & 7) * 8;
                #pragma unroll
                for (int bb = 0; bb < 8; bb++)
                    o += qa[bb] * ka[(j - bb) & 7];
            }
            sm[OFF_OUT + px * 68 + ch] = o;
        }
    }
    __syncthreads();

    // ---- dense write of attn+v ----
    for (int i = tid; i < 64 * 16; i += 512) {
        int px = i >> 4, v = i & 15;
        int gi = px >> 3, gj = px & 7;
        size_t gp = (size_t)b * HWSZ + (ph * 8 + gi) * WW + (pw * 8 + gj);
        *(float4*)(g_av + gp * 64 + v * 4) = *(float4*)(sm + OFF_OUT + px * 68 + v * 4);
    }
}

// ---------------- DO: LN, *v, fp, silu gate, W2e, + g_ox ----------------
// per-expert 5216: fp 1024 | p1 2048 | W2 2048 | fpb 32 | lnw 32 | lnb 32
#define DO_SMEM 20864
__global__ __launch_bounds__(256) void k_DO(const float* __restrict__ sh,
                                            const float* __restrict__ fpw,
                                            const float* __restrict__ fpb,
                                            const float* __restrict__ p1w,
                                            const float* __restrict__ lnw,
                                            const float* __restrict__ lnb,
                                            float* __restrict__ out) {
    extern __shared__ float smd[];
    int tid = threadIdx.x;
    for (int i = tid; i < 4096; i += 256) smd[(i >> 10) * 5216 + (i & 1023)] = fpw[i];
    for (int i = tid; i < 8192; i += 256) smd[(i >> 11) * 5216 + 1024 + (i & 2047)] = p1w[i];
    for (int i = tid; i < 8192; i += 256) smd[(i >> 11) * 5216 + 3072 + (i & 2047)] = g_W2[i];
    if (tid < 128) {
        smd[(tid >> 5) * 5216 + 5120 + (tid & 31)] = fpb[tid];
        smd[(tid >> 5) * 5216 + 5152 + (tid & 31)] = lnw[tid];
        smd[(tid >> 5) * 5216 + 5184 + (tid & 31)] = lnb[tid];
    }
    __syncthreads();

    int p = blockIdx.x * 256 + tid;
    int b = p >> 16, s = p & 0xFFFF;
    int e = g_idx[p];
    float m = g_gate[p];
    const float* base_ = smd + e * 5216;
    const float* s_fp  = base_;
    const float* s_p1  = base_ + 1024;
    const float* s_W2  = base_ + 3072;
    const float* s_fpb = base_ + 5120;
    const float* s_lnw = base_ + 5152;
    const float* s_lnb = base_ + 5184;

    // 1. gate dots from shared path
    float gg[32];
    {
        float shv[64];
        const float* shb = sh + ((size_t)b * DIM) * HWSZ + s;
        #pragma unroll
        for (int c = 0; c < 64; c++) shv[c] = shb[(size_t)c * HWSZ];
        #pragma unroll 2
        for (int o = 0; o < 32; o++) {
            const float4* pr = (const float4*)(s_p1 + o * 64);
            float g = 0.f;
            #pragma unroll
            for (int j = 0; j < 16; j++) {
                float4 w = pr[j];
                g += w.x * shv[4*j] + w.y * shv[4*j+1] + w.z * shv[4*j+2] + w.w * shv[4*j+3];
            }
            gg[o] = g;
        }
    }

    // 2. LN(attn) * v
    const float* av = g_av + (size_t)p * 64;
    float t[32], vv[32];
    #pragma unroll
    for (int j = 0; j < 8; j++) {
        float4 a4 = *(const float4*)(av + j * 4);
        t[4*j] = a4.x; t[4*j+1] = a4.y; t[4*j+2] = a4.z; t[4*j+3] = a4.w;
        float4 v4 = *(const float4*)(av + 32 + j * 4);
        vv[4*j] = v4.x; vv[4*j+1] = v4.y; vv[4*j+2] = v4.z; vv[4*j+3] = v4.w;
    }
    float sum = 0.f, sq = 0.f;
    #pragma unroll
    for (int r = 0; r < 32; r++) { sum += t[r]; sq += t[r] * t[r]; }
    float mean = sum * (1.f / 32.f);
    float var  = sq * (1.f / 32.f) - mean * mean;
    float inv  = rsqrtf(var + 1e-5f);
    #pragma unroll
    for (int r = 0; r < 32; r++)
        t[r] = ((t[r] - mean) * inv * s_lnw[r] + s_lnb[r]) * vv[r];

    // 3. body * silu gate
    float bg[32];
    #pragma unroll 2
    for (int o = 0; o < 32; o++) {
        const float4* fr = (const float4*)(s_fp + o * 32);
        float acc = s_fpb[o];
        #pragma unroll
        for (int j = 0; j < 8; j++) {
            float4 w = fr[j];
            acc += w.x * t[4*j] + w.y * t[4*j+1] + w.z * t[4*j+2] + w.w * t[4*j+3];
        }
        float z = m * gg[o];
        float sg = z / (1.f + expf(-z));
        bg[o] = acc * sg;
    }

    // 4. out = m*(W2e@bg) + g_ox   (g_ox already holds m^2*(ow@x)+outb)
    const float4* oxp4 = (const float4*)(g_ox + (size_t)p * 64);
    float* ob_ = out + ((size_t)b * DIM) * HWSZ + s;
    #pragma unroll 2
    for (int og = 0; og < 16; og++) {
        float4 ox4 = oxp4[og];
        #pragma unroll
        for (int u = 0; u < 4; u++) {
            int o = og * 4 + u;
            const float4* wr = (const float4*)(s_W2 + o * 32);
            float acc = 0.f;
            #pragma unroll
            for (int j = 0; j < 8; j++) {
                float4 w = wr[j];
                acc += w.x * bg[4*j] + w.y * bg[4*j+1] + w.z * bg[4*j+2] + w.w * bg[4*j+3];
            }
            float oxo = (u == 0) ? ox4.x : (u == 1) ? ox4.y : (u == 2) ? ox4.z : ox4.w;
            ob_[(size_t)o * HWSZ] = m * acc + oxo;
        }
    }
}

// ---------------- launch ----------------
extern "C" void kernel_launch(void* const* d_in, const int* in_sizes, int n_in,
                              void* d_out, int out_size) {
    const float* x     = (const float*)d_in[0];
    const float* sh    = (const float*)d_in[1];
    const float* rw    = (const float*)d_in[2];
    const float* rb    = (const float*)d_in[3];
    const float* p0w   = (const float*)d_in[4];
    const float* p1w   = (const float*)d_in[5];
    const float* p2w   = (const float*)d_in[6];
    const float* qw    = (const float*)d_in[7];
    const float* qdww  = (const float*)d_in[8];
    const float* qdwb  = (const float*)d_in[9];
    const float* kvw   = (const float*)d_in[10];
    const float* kvdww = (const float*)d_in[11];
    const float* kvdwb = (const float*)d_in[12];
    const float* lnw   = (const float*)d_in[13];
    const float* lnb   = (const float*)d_in[14];
    const float* fpw   = (const float*)d_in[15];
    const float* fpb   = (const float*)d_in[16];
    const float* outw  = (const float*)d_in[17];
    const float* outb  = (const float*)d_in[18];
    float* out = (float*)d_out;

    static int inited = 0;
    if (!inited) {
        cudaFuncSetAttribute(k_AR, cudaFuncAttributeMaxDynamicSharedMemorySize, AR_SMEM * 4);
        cudaFuncSetAttribute(k_B,  cudaFuncAttributeMaxDynamicSharedMemorySize, SMEM_B_FLOATS * 4);
        cudaFuncSetAttribute(k_DO, cudaFuncAttributeMaxDynamicSharedMemorySize, DO_SMEM * 4);
        inited = 1;
    }

    k_prep<<<128, 256>>>(qw, kvw, p0w, p2w, outw);
    k_AR<<<NPIX / 256, 256, AR_SMEM * 4>>>(x, rw, rb, outw, outb);
    k_B<<<BB * 1024, 512, SMEM_B_FLOATS * 4>>>(qdww, qdwb, kvdww, kvdwb);
    k_DO<<<NPIX / 256, 256, DO_SMEM * 4>>>(sh, fpw, fpb, p1w, lnw, lnb, out);
}

// round 11
// speedup vs baseline: 1.1866x; 1.1076x over previous
#include <cuda_runtime.h>

// ---------------- problem constants ----------------
#define BB    4
#define DIM   64
#define RANK  32
#define EE    4
#define HH    256
#define WW    256
#define HWSZ  65536
#define NPIX  262144

// ---------------- device scratch ----------------
__device__ float g_gate[NPIX];
__device__ int   g_idx[NPIX];
__device__ float g_W[4 * 96 * 64];           // fused [Wq;Wkv] per expert
__device__ float g_pre[(size_t)NPIX * 96];   // [p][0:32)=qpre, [32:96)=kvpre

// ---------------- prep: fold q_w@p0_w / kv_w@p0_w ----------------
__global__ void k_prep(const float* __restrict__ qw,
                       const float* __restrict__ kvw,
                       const float* __restrict__ p0) {
    int i = blockIdx.x * blockDim.x + threadIdx.x;     // < 24576
    int e = i / 6144;
    int rem = i - e * 6144;
    int o = rem >> 6, c = rem & 63;
    const float* p0e = p0 + e * 2048;
    float acc = 0.f;
    if (o < 32) {
        const float* qe = qw + e * 1024 + o * 32;
        #pragma unroll
        for (int r = 0; r < 32; r++) acc += qe[r] * p0e[r * 64 + c];
    } else {
        const float* ke = kvw + e * 2048 + (o - 32) * 32;
        #pragma unroll
        for (int r = 0; r < 32; r++) acc += ke[r] * p0e[r * 64 + c];
    }
    g_W[i] = acc;
}

// ---------------- AR: fused router + 1x1 conv -> g_pre ----------------
#define AR_SMEM 24836
__global__ __launch_bounds__(256) void k_AR(const float* __restrict__ x,
                                            const float* __restrict__ rw,
                                            const float* __restrict__ rb) {
    extern __shared__ float sW[];     // 24576 W | rw 256 | rb 4
    int tid = threadIdx.x;
    for (int i = tid; i < 24576; i += 256) sW[i] = g_W[i];
    if (tid < 256) sW[24576 + tid] = rw[tid];
    if (tid < 4)   sW[24832 + tid] = rb[tid];
    __syncthreads();

    int p = blockIdx.x * 256 + tid;
    int b = p >> 16, s = p & 0xFFFF;
    const float* xb = x + ((size_t)b * DIM) * HWSZ + s;
    float xv[64];
    #pragma unroll
    for (int c = 0; c < 64; c++) xv[c] = xb[(size_t)c * HWSZ];

    const float* srw = sW + 24576;
    float l0 = sW[24832], l1 = sW[24833], l2 = sW[24834], l3 = sW[24835];
    #pragma unroll
    for (int c = 0; c < 64; c++) {
        float v = xv[c];
        l0 += srw[c] * v; l1 += srw[64 + c] * v;
        l2 += srw[128 + c] * v; l3 += srw[192 + c] * v;
    }
    float lm = l0; int am = 0;
    if (l1 > lm) { lm = l1; am = 1; }
    if (l2 > lm) { lm = l2; am = 2; }
    if (l3 > lm) { lm = l3; am = 3; }
    float m = 1.0f / (expf(l0 - lm) + expf(l1 - lm) + expf(l2 - lm) + expf(l3 - lm));
    g_gate[p] = m;
    g_idx[p]  = am;

    #pragma unroll
    for (int c = 0; c < 64; c++) xv[c] *= m;      // xv = m*x

    const float4* Wv = (const float4*)(sW + am * 6144);
    float* op = g_pre + (size_t)p * 96;
    #pragma unroll 2
    for (int og = 0; og < 24; og++) {
        float r[4];
        #pragma unroll
        for (int u = 0; u < 4; u++) {
            const float4* wr = Wv + (og * 4 + u) * 16;
            float acc = 0.f;
            #pragma unroll
            for (int j = 0; j < 16; j++) {
                float4 w = wr[j];
                acc += w.x * xv[4*j] + w.y * xv[4*j+1] + w.z * xv[4*j+2] + w.w * xv[4*j+3];
            }
            r[u] = acc;
        }
        *(float4*)(op + og * 4) = make_float4(r[0], r[1], r[2], r[3]);
    }
}

// ---------------- B: dwconv + circular conv + precise epilogue ----------------
#define OFF_KV   0          // 196*64 = 12544
#define OFF_QT   12544      // 100*32 = 3200
#define OFF_QE   15744      // 4*2081
#define OFF_KE   24068      // 4*2081
#define OFF_OUT  32392      // 64*68 (live: attn/v, later comb)
#define OFF_W7   36744      // 4*64*49
#define OFF_W3   49288      // 4*32*9
#define OFF_B7   50440      // 256
#define OFF_B3   50696      // 128
#define OFF_IDX  50824      // 196 ints
#define SMEM_B_FLOATS 51020
#define ESTRIDE  2081
// epilogue aliases (all regions dead after circular conv except OFF_OUT/OFF_IDX):
#define EP_EW    0          // 4*5728: fp(32x36)@0 | p1(32x68)@1152 | p2(64x36)@3328 | fpb@5632 lnw@5664 lnb@5696
#define EP_SH    24068      // 64*68 = 4352  (in dead KE region, ends 28420 < 32392)
#define EP_X     36744      // 64*68 = 4352  (in dead W7 region)
#define EP_OW    41096      // 64*68 = 4352
#define EP_BG    45448      // 64*40 = 2560
#define EP_GATE  48008      // 64
#define EP_EIX   48072      // 64 ints
#define EP_OB    48136      // 64  (ends 48200 < 50824)

__global__ __launch_bounds__(512) void k_B(const float* __restrict__ qdww,
                                           const float* __restrict__ qdwb,
                                           const float* __restrict__ kvdww,
                                           const float* __restrict__ kvdwb,
                                           const float* __restrict__ x,
                                           const float* __restrict__ sh,
                                           const float* __restrict__ fpw,
                                           const float* __restrict__ fpb,
                                           const float* __restrict__ p1w,
                                           const float* __restrict__ p2w,
                                           const float* __restrict__ lnw,
                                           const float* __restrict__ lnb,
                                           const float* __restrict__ ow,
                                           const float* __restrict__ ob,
                                           float* __restrict__ out) {
    extern __shared__ float sm[];
    int* sIdx = (int*)(sm + OFF_IDX);
    int tid = threadIdx.x;
    int blk = blockIdx.x;
    int b = blk >> 10, sp = blk & 1023, ph = sp >> 5, pw = sp & 31;
    int y0 = ph * 8 - 3, x0 = pw * 8 - 3;

    // ---- halos + owner map ----
    for (int i = tid; i < 196; i += 512) {
        int hy = i / 14, hx = i - hy * 14;
        int gy = y0 + hy, gx = x0 + hx;
        sIdx[i] = (gy >= 0 && gy < HH && gx >= 0 && gx < WW)
                ? g_idx[b * HWSZ + gy * WW + gx] : -1;
    }
    for (int i = tid; i < 196 * 16; i += 512) {
        int px = i >> 4, v = i & 15;
        int hy = px / 14, hx = px - hy * 14;
        int gy = y0 + hy, gx = x0 + hx;
        float4 val = make_float4(0.f, 0.f, 0.f, 0.f);
        if (gy >= 0 && gy < HH && gx >= 0 && gx < WW)
            val = *(const float4*)(g_pre + ((size_t)(b * HWSZ + gy * WW + gx)) * 96 + 32 + v * 4);
        *(float4*)(sm + OFF_KV + px * 64 + v * 4) = val;
    }
    for (int i = tid; i < 100 * 8; i += 512) {
        int px = i >> 3, v = i & 7;
        int hy = px / 10, hx = px - hy * 10;
        int gy = y0 + 2 + hy, gx = x0 + 2 + hx;
        float4 val = make_float4(0.f, 0.f, 0.f, 0.f);
        if (gy >= 0 && gy < HH && gx >= 0 && gx < WW)
            val = *(const float4*)(g_pre + ((size_t)(b * HWSZ + gy * WW + gx)) * 96 + v * 4);
        *(float4*)(sm + OFF_QT + px * 32 + v * 4) = val;
    }
    __syncthreads();

    // ---- expert presence ----
    int bit = 0;
    if (tid < 64) {
        int i = tid >> 3, j = tid & 7;
        bit = 1 << sIdx[(i + 3) * 14 + (j + 3)];
    }
    int mask = __syncthreads_or(bit);

    // ---- stage dw weights for present experts ----
    for (int e = 0; e < 4; e++) {
        if (!((mask >> e) & 1)) continue;
        for (int i = tid; i < 3136; i += 512) sm[OFF_W7 + e * 3136 + i] = kvdww[e * 3136 + i];
        if (tid < 288) sm[OFF_W3 + e * 288 + tid] = qdww[e * 288 + tid];
        if (tid < 64)  sm[OFF_B7 + e * 64 + tid]  = kvdwb[e * 64 + tid];
        if (tid < 32)  sm[OFF_B3 + e * 32 + tid]  = qdwb[e * 32 + tid];
    }
    __syncthreads();

    // ---- dw7 per present expert ----
    {
        int ch = tid & 63, row = tid >> 6;
        for (int e = 0; e < 4; e++) {
            if (!((mask >> e) & 1)) continue;
            float bv = sm[OFF_B7 + e * 64 + ch];
            float acc[8];
            #pragma unroll
            for (int j = 0; j < 8; j++) acc[j] = bv;
            #pragma unroll
            for (int ky = 0; ky < 7; ky++) {
                const float* inr = sm + OFF_KV + (row + ky) * 896 + ch;
                const int*   owr = sIdx + (row + ky) * 14;
                float me[14];
                #pragma unroll
                for (int xx = 0; xx < 14; xx++)
                    me[xx] = (owr[xx] == e) ? inr[xx * 64] : 0.f;
                const float* wr = sm + OFF_W7 + (e * 64 + ch) * 49 + ky * 7;
                #pragma unroll
                for (int kx = 0; kx < 7; kx++) {
                    float w = wr[kx];
                    #pragma unroll
                    for (int j = 0; j < 8; j++) acc[j] += w * me[j + kx];
                }
            }
            if (ch < 32) {
                float* kd = sm + OFF_KE + e * ESTRIDE + ch * 65 + row * 8;
                #pragma unroll
                for (int j = 0; j < 8; j++) kd[j] = acc[j];
            } else {
                #pragma unroll
                for (int j = 0; j < 8; j++) {
                    int own = sIdx[(row + 3) * 14 + (j + 3)];
                    if (own == e) sm[OFF_OUT + (row * 8 + j) * 68 + ch] = acc[j];
                }
            }
        }
    }

    // ---- dw3 per present expert ----
    if (tid < 256) {
        int ch = tid & 31, row = tid >> 5;
        for (int e = 0; e < 4; e++) {
            if (!((mask >> e) & 1)) continue;
            float bv = sm[OFF_B3 + e * 32 + ch];
            float acc[8];
            #pragma unroll
            for (int j = 0; j < 8; j++) acc[j] = bv;
            #pragma unroll
            for (int ky = 0; ky < 3; ky++) {
                const float* inr = sm + OFF_QT + (row + ky) * 320 + ch;
                const int*   owr = sIdx + (row + ky + 2) * 14 + 2;
                float me[10];
                #pragma unroll
                for (int xx = 0; xx < 10; xx++)
                    me[xx] = (owr[xx] == e) ? inr[xx * 32] : 0.f;
                const float* wr = sm + OFF_W3 + (e * 32 + ch) * 9 + ky * 3;
                #pragma unroll
                for (int kx = 0; kx < 3; kx++) {
                    float w = wr[kx];
                    #pragma unroll
                    for (int j = 0; j < 8; j++) acc[j] += w * me[j + kx];
                }
            }
            float* qd = sm + OFF_QE + e * ESTRIDE + ch * 65 + row * 8;
            #pragma unroll
            for (int j = 0; j < 8; j++) qd[j] = acc[j];
        }
    }
    __syncthreads();

    // ---- circular conv per pixel with owner's q,k -> OUT ch 0..31 ----
    {
        int ch = tid >> 4;
        int g4 = (tid & 15) * 4;
        #pragma unroll
        for (int pp = 0; pp < 4; pp++) {
            int px = g4 + pp;
            int i = px >> 3, j = px & 7;
            int e = sIdx[(i + 3) * 14 + (j + 3)];
            const float* q = sm + OFF_QE + e * ESTRIDE + ch * 65;
            const float* k = sm + OFF_KE + e * ESTRIDE + ch * 65;
            float o = 0.f;
            #pragma unroll
            for (int a = 0; a < 8; a++) {
                const float* qa = q + a * 8;
                const float* ka = k + ((i - a) & 7) * 8;
                #pragma unroll
                for (int bb = 0; bb < 8; bb++)
                    o += qa[bb] * ka[(j - bb) & 7];
            }
            sm[OFF_OUT + px * 68 + ch] = o;
        }
    }
    __syncthreads();   // all pre-epilogue regions except OUT/sIdx now dead

    // ---- stage epilogue weights (present experts) + sh, x, ow, gate, owner ----
    for (int e = 0; e < 4; e++) {
        if (!((mask >> e) & 1)) continue;
        float* eb = sm + EP_EW + e * 5728;
        for (int i = tid; i < 1024; i += 512) eb[(i >> 5) * 36 + (i & 31)] = fpw[e * 1024 + i];
        for (int i = tid; i < 2048; i += 512) eb[1152 + (i >> 6) * 68 + (i & 63)] = p1w[e * 2048 + i];
        for (int i = tid; i < 2048; i += 512) eb[3328 + (i >> 5) * 36 + (i & 31)] = p2w[e * 2048 + i];
        if (tid < 32) {
            eb[5632 + tid] = fpb[e * 32 + tid];
            eb[5664 + tid] = lnw[e * 32 + tid];
            eb[5696 + tid] = lnb[e * 32 + tid];
        }
    }
    for (int i = tid; i < 4096; i += 512) {
        int px = i & 63, c = i >> 6;
        int gy = ph * 8 + (px >> 3), gx = pw * 8 + (px & 7);
        size_t goff = (((size_t)(b * 64 + c)) << 16) + gy * WW + gx;
        sm[EP_SH + px * 68 + c] = sh[goff];
        sm[EP_X  + px * 68 + c] = x[goff];
    }
    for (int i = tid; i < 4096; i += 512)
        sm[EP_OW + (i >> 6) * 68 + (i & 63)] = ow[i];
    if (tid < 64) {
        sm[EP_OB + tid] = ob[tid];
        int gy = ph * 8 + (tid >> 3), gx = pw * 8 + (tid & 7);
        sm[EP_GATE + tid] = g_gate[b * HWSZ + gy * WW + gx];
        ((int*)(sm + EP_EIX))[tid] = sIdx[((tid >> 3) + 3) * 14 + (tid & 7) + 3];
    }
    __syncthreads();

    int px = tid >> 3, r = tid & 7;

    // ---- LN(attn)*v in place ----
    {
        int e = ((int*)(sm + EP_EIX))[px];
        const float* eb = sm + EP_EW + e * 5728;
        float4 a4 = *(float4*)(sm + OFF_OUT + px * 68 + r * 4);
        float4 v4 = *(float4*)(sm + OFF_OUT + px * 68 + 32 + r * 4);
        float sum = a4.x + a4.y + a4.z + a4.w;
        float sq  = a4.x*a4.x + a4.y*a4.y + a4.z*a4.z + a4.w*a4.w;
        #pragma unroll
        for (int off = 1; off < 8; off <<= 1) {
            sum += __shfl_xor_sync(0xffffffffu, sum, off, 8);
            sq  += __shfl_xor_sync(0xffffffffu, sq,  off, 8);
        }
        float mean = sum * (1.f / 32.f);
        float var  = sq * (1.f / 32.f) - mean * mean;
        float inv  = rsqrtf(var + 1e-5f);
        float4 t4;
        t4.x = ((a4.x - mean) * inv * eb[5664 + r*4    ] + eb[5696 + r*4    ]) * v4.x;
        t4.y = ((a4.y - mean) * inv * eb[5664 + r*4 + 1] + eb[5696 + r*4 + 1]) * v4.y;
        t4.z = ((a4.z - mean) * inv * eb[5664 + r*4 + 2] + eb[5696 + r*4 + 2]) * v4.z;
        t4.w = ((a4.w - mean) * inv * eb[5664 + r*4 + 3] + eb[5696 + r*4 + 3]) * v4.w;
        *(float4*)(sm + OFF_OUT + px * 68 + r * 4) = t4;
    }
    __syncthreads();

    // ---- bg = (fp@t + fpb) * silu(m * (p1@sh)) ----
    {
        int e = ((int*)(sm + EP_EIX))[px];
        float m = sm[EP_GATE + px];
        const float* eb = sm + EP_EW + e * 5728;
        const float4* tn  = (const float4*)(sm + OFF_OUT + px * 68);
        const float4* shv = (const float4*)(sm + EP_SH + px * 68);
        #pragma unroll
        for (int oo = 0; oo < 4; oo++) {
            int o = r + oo * 8;
            const float4* fr = (const float4*)(eb + o * 36);
            float facc = eb[5632 + o];
            #pragma unroll
            for (int j = 0; j < 8; j++) {
                float4 w = fr[j]; float4 t = tn[j];
                facc += w.x * t.x + w.y * t.y + w.z * t.z + w.w * t.w;
            }
            const float4* pr = (const float4*)(eb + 1152 + o * 68);
            float gg = 0.f;
            #pragma unroll
            for (int j = 0; j < 16; j++) {
                float4 w = pr[j]; float4 sv = shv[j];
                gg += w.x * sv.x + w.y * sv.y + w.z * sv.z + w.w * sv.w;
            }
            float z = m * gg;
            float sg = z / (1.f + expf(-z));
            sm[EP_BG + px * 40 + o] = facc * sg;
        }
    }
    __syncthreads();

    // ---- comb = m*(p2@bg) + m^2*x  -> OUT (overwrites t/v, both dead) ----
    {
        int e = ((int*)(sm + EP_EIX))[px];
        float m = sm[EP_GATE + px];
        float m2 = m * m;
        const float* eb = sm + EP_EW + e * 5728;
        float4 bgv[8];
        #pragma unroll
        for (int j = 0; j < 8; j++) bgv[j] = ((float4*)(sm + EP_BG + px * 40))[j];
        #pragma unroll
        for (int oo = 0; oo < 8; oo++) {
            int o = r + oo * 8;
            const float4* pr = (const float4*)(eb + 3328 + o * 36);
            float acc = 0.f;
            #pragma unroll
            for (int j = 0; j < 8; j++) {
                float4 w = pr[j]; float4 bb = bgv[j];
                acc += w.x * bb.x + w.y * bb.y + w.z * bb.z + w.w * bb.w;
            }
            sm[OFF_OUT + px * 68 + o] = m * acc + m2 * sm[EP_X + px * 68 + o];
        }
    }
    __syncthreads();

    // ---- out = ow@comb + outb  (precise association) -> EP_X (dead) ----
    {
        float4 cv[16];
        #pragma unroll
        for (int j = 0; j < 16; j++) cv[j] = ((float4*)(sm + OFF_OUT + px * 68))[j];
        #pragma unroll
        for (int oo = 0; oo < 8; oo++) {
            int o = r + oo * 8;
            const float4* wr = (const float4*)(sm + EP_OW + o * 68);
            float acc = sm[EP_OB + o];
            #pragma unroll
            for (int j = 0; j < 16; j++) {
                float4 w = wr[j]; float4 c = cv[j];
                acc += w.x * c.x + w.y * c.y + w.z * c.z + w.w * c.w;
            }
            sm[EP_X + px * 68 + o] = acc;
        }
    }
    __syncthreads();

    // ---- coalesced planar write-out ----
    for (int i = tid; i < 4096; i += 512) {
        int qx = i & 63, o = i >> 6;
        int gy = ph * 8 + (qx >> 3), gx = pw * 8 + (qx & 7);
        out[(((size_t)(b * 64 + o)) << 16) + gy * WW + gx] = sm[EP_X + qx * 68 + o];
    }
}

// ---------------- launch ----------------
extern "C" void kernel_launch(void* const* d_in, const int* in_sizes, int n_in,
                              void* d_out, int out_size) {
    const float* x     = (const float*)d_in[0];
    const float* sh    = (const float*)d_in[1];
    const float* rw    = (const float*)d_in[2];
    const float* rb    = (const float*)d_in[3];
    const float* p0w   = (const float*)d_in[4];
    const float* p1w   = (const float*)d_in[5];
    const float* p2w   = (const float*)d_in[6];
    const float* qw    = (const float*)d_in[7];
    const float* qdww  = (const float*)d_in[8];
    const float* qdwb  = (const float*)d_in[9];
    const float* kvw   = (const float*)d_in[10];
    const float* kvdww = (const float*)d_in[11];
    const float* kvdwb = (const float*)d_in[12];
    const float* lnw   = (const float*)d_in[13];
    const float* lnb   = (const float*)d_in[14];
    const float* fpw   = (const float*)d_in[15];
    const float* fpb   = (const float*)d_in[16];
    const float* outw  = (const float*)d_in[17];
    const float* outb  = (const float*)d_in[18];
    float* out = (float*)d_out;

    static int inited = 0;
    if (!inited) {
        cudaFuncSetAttribute(k_AR, cudaFuncAttributeMaxDynamicSharedMemorySize, AR_SMEM * 4);
        cudaFuncSetAttribute(k_B,  cudaFuncAttributeMaxDynamicSharedMemorySize, SMEM_B_FLOATS * 4);
        inited = 1;
    }

    k_prep<<<96, 256>>>(qw, kvw, p0w);
    k_AR<<<NPIX / 256, 256, AR_SMEM * 4>>>(x, rw, rb);
    k_B<<<BB * 1024, 512, SMEM_B_FLOATS * 4>>>(qdww, qdwb, kvdww, kvdwb,
                                               x, sh, fpw, fpb, p1w, p2w,
                                               lnw, lnb, outw, outb, out);
}